// round 2
// baseline (speedup 1.0000x reference)
#include <cuda_runtime.h>
#include <cstdint>

#define B_   512
#define T_   2048
#define D_   64
#define H_   66
#define G4   264         // 4*H
#define BPB  4           // batches per block
#define NBLK (B_ / BPB)  // 128 blocks -> single wave on 148 SMs

__device__ float    g_hT[B_ * H_];
__device__ unsigned g_done = 0;

// ---- packed f32x2 helpers (sm_103a FFMA2 path) ----
#define FMA2(d, a, b, c) asm("fma.rn.f32x2 %0, %1, %2, %3;" : "=l"(d) : "l"(a), "l"(b), "l"(c))
#define ADD2(d, a, b)    asm("add.rn.f32x2 %0, %1, %2;"     : "=l"(d) : "l"(a), "l"(b))
#define PACK2(d, lo, hi) asm("mov.b64 %0, {%1, %2};"        : "=l"(d) : "f"(lo), "f"(hi))
#define UNPACK2(lo, hi, s) asm("mov.b64 {%0, %1}, %2;"      : "=f"(lo), "=f"(hi) : "l"(s))

__global__ __launch_bounds__(G4, 1) void fused_lstm_kernel(
    const float* __restrict__ x,     const float* __restrict__ W_ih,
    const float* __restrict__ W_hh,  const float* __restrict__ b_ih,
    const float* __restrict__ b_hh,  const float* __restrict__ gamma,
    const float* __restrict__ beta,  const float* __restrict__ fc_w,
    const float* __restrict__ fc_b,  float* __restrict__ out)
{
    __shared__ __align__(16) float sh_h[BPB][H_ + 2];  // h per batch, padded for LDS.128
    __shared__ __align__(16) float sh_x[BPB][D_];      // staged x rows (single buffer)
    __shared__ float sh_g[BPB][G4];                    // activated gates
    __shared__ float s_a[H_], s_b[H_];
    __shared__ unsigned s_last;

    const int g  = threadIdx.x;
    const int b0 = blockIdx.x * BPB;

    // ---- register-resident weights ----
    unsigned long long wih[D_ / 2];                 // 32 packed f32x2
    {
        const ulonglong2* wp = (const ulonglong2*)(W_ih + (size_t)g * D_);
        #pragma unroll
        for (int i = 0; i < D_ / 4; i++) { ulonglong2 v = wp[i]; wih[2*i] = v.x; wih[2*i+1] = v.y; }
    }
    unsigned long long whh[34];                     // 33 real + 1 zero (covers pad)
    {
        const float* wr = W_hh + (size_t)g * H_;
        #pragma unroll
        for (int i = 0; i < 33; i++) PACK2(whh[i], wr[2*i], wr[2*i + 1]);
        PACK2(whh[33], 0.f, 0.f);
    }
    const float bias = b_ih[g] + b_hh[g];

    // ---- init ----
    for (int i = g; i < BPB * (H_ + 2); i += G4) ((float*)sh_h)[i] = 0.f;
    const int q0 = g / H_, r = g % H_;              // this thread's (batch-slot, feature) for the update phase
    float c_ = 0.f, h_ = 0.f;
    const bool tg = (g >= 2 * H_) && (g < 3 * H_);  // tanh gate?

    // ---- prologue: stage x_0 and compute xp_0 ----
    if (g < BPB * D_)
        sh_x[g >> 6][g & 63] = x[(size_t)(b0 + (g >> 6)) * T_ * D_ + (g & 63)];
    __syncthreads();

    float xp[BPB];
    #pragma unroll
    for (int q = 0; q < BPB; q++) {
        const ulonglong2* hp = (const ulonglong2*)sh_x[q];
        unsigned long long a0, a1 = 0ull; PACK2(a0, bias, 0.f);
        #pragma unroll
        for (int k = 0; k < D_ / 4; k++) { ulonglong2 v = hp[k]; FMA2(a0, wih[2*k], v.x, a0); FMA2(a1, wih[2*k+1], v.y, a1); }
        ADD2(a0, a0, a1); float lo, hi; UNPACK2(lo, hi, a0); xp[q] = lo + hi;
    }
    __syncthreads();

    // ---- recurrence ----
    for (int t = 0; t < T_; t++) {
        // stage x_{t+1} (read next step, WAR-safe: prior reads fenced by last barrier)
        if (g < BPB * D_ && t + 1 < T_)
            sh_x[g >> 6][g & 63] =
                x[(size_t)(b0 + (g >> 6)) * T_ * D_ + (size_t)(t + 1) * D_ + (g & 63)];

        // gate pre-activations + activation, 4 batches with shared weight regs
        #pragma unroll
        for (int q = 0; q < BPB; q++) {
            const ulonglong2* hp = (const ulonglong2*)sh_h[q];
            unsigned long long a0 = 0ull, a1 = 0ull;
            #pragma unroll
            for (int k = 0; k < 17; k++) { ulonglong2 v = hp[k]; FMA2(a0, whh[2*k], v.x, a0); FMA2(a1, whh[2*k+1], v.y, a1); }
            ADD2(a0, a0, a1); float lo, hi; UNPACK2(lo, hi, a0);
            const float pre = lo + hi + xp[q];
            const float arg = tg ? (-2.f * pre) : (-pre);
            const float e   = __expf(arg);
            const float s   = __fdividef(1.f, 1.f + e);
            sh_g[q][g] = tg ? (2.f * s - 1.f) : s;
        }
        __syncthreads();

        // c/h update: every thread owns one (batch-slot, feature) cell
        {
            const float i_ = sh_g[q0][r];
            const float f_ = sh_g[q0][H_ + r];
            const float gg = sh_g[q0][2 * H_ + r];
            const float o_ = sh_g[q0][3 * H_ + r];
            c_ = f_ * c_ + i_ * gg;
            const float e2 = __expf(-2.f * c_);
            const float th = __fdividef(2.f, 1.f + e2) - 1.f;
            h_ = o_ * th;
            sh_h[q0][r] = h_;
        }

        // x-projection for t+1 (independent of h -> fills latency)
        #pragma unroll
        for (int q = 0; q < BPB; q++) {
            const ulonglong2* hp = (const ulonglong2*)sh_x[q];
            unsigned long long a0, a1 = 0ull; PACK2(a0, bias, 0.f);
            #pragma unroll
            for (int k = 0; k < D_ / 4; k++) { ulonglong2 v = hp[k]; FMA2(a0, wih[2*k], v.x, a0); FMA2(a1, wih[2*k+1], v.y, a1); }
            ADD2(a0, a0, a1); float lo, hi; UNPACK2(lo, hi, a0); xp[q] = lo + hi;
        }
        __syncthreads();
    }

    // ---- publish h_T, elect last block ----
    g_hT[(b0 + q0) * H_ + r] = h_;
    __threadfence();
    if (g == 0) {
        unsigned old = atomicAdd(&g_done, 1);
        s_last = (old == NBLK - 1) ? 1u : 0u;
    }
    __syncthreads();
    if (!s_last) return;
    if (g == 0) g_done = 0;   // reset for deterministic graph replays
    __threadfence();

    // ---- BN stats (last block): feature r, batch-chunk q0 ----
    {
        float s = 0.f, qs = 0.f;
        for (int b = q0 * (B_ / BPB); b < (q0 + 1) * (B_ / BPB); b++) {
            const float v = g_hT[b * H_ + r];
            s += v; qs += v * v;
        }
        sh_g[q0][r] = s;
        sh_h[q0][r] = qs;
    }
    __syncthreads();
    if (q0 == 0) {
        const float S = sh_g[0][r] + sh_g[1][r] + sh_g[2][r] + sh_g[3][r];
        const float Q = sh_h[0][r] + sh_h[1][r] + sh_h[2][r] + sh_h[3][r];
        const float mean = S * (1.f / B_);
        const float var  = Q * (1.f / B_) - mean * mean;
        const float a    = gamma[r] * rsqrtf(var + 1e-5f);
        const float bb   = beta[r] - mean * a;
        s_a[r] = a * fc_w[r];
        s_b[r] = bb * fc_w[r];
    }
    __syncthreads();

    // ---- head: logits[b] = fc_b + sum_j s_a[j]*h[b,j] + s_b[j] ----
    const float f0 = fc_b[0];
    for (int b = g; b < B_; b += G4) {
        float acc = f0;
        #pragma unroll
        for (int j = 0; j < H_; j++)
            acc += s_a[j] * g_hT[b * H_ + j] + s_b[j];
        out[b] = acc;
    }
}

extern "C" void kernel_launch(void* const* d_in, const int* in_sizes, int n_in,
                              void* d_out, int out_size)
{
    const float* x     = (const float*)d_in[0];
    const float* W_ih  = (const float*)d_in[1];
    const float* W_hh  = (const float*)d_in[2];
    const float* b_ih  = (const float*)d_in[3];
    const float* b_hh  = (const float*)d_in[4];
    const float* gamma = (const float*)d_in[5];
    const float* beta  = (const float*)d_in[6];
    const float* fc_w  = (const float*)d_in[7];
    const float* fc_b  = (const float*)d_in[8];
    float* out = (float*)d_out;

    fused_lstm_kernel<<<NBLK, G4>>>(x, W_ih, W_hh, b_ih, b_hh,
                                    gamma, beta, fc_w, fc_b, out);
}

// round 3
// speedup vs baseline: 1.3092x; 1.3092x over previous
#include <cuda_runtime.h>
#include <cstdint>

#define B_     512
#define T_     2048
#define D_     64
#define H_     66
#define G4     264            // 4*H
#define BPB    4              // batches per block
#define NBLK   (B_ / BPB)     // 128 blocks -> one wave
#define NTHR   576            // 288 gate-role + 288 proj-role threads
#define GATE_T 288

__device__ float    g_hT[B_ * H_];
__device__ unsigned g_done = 0;

// ---- packed f32x2 helpers (sm_103a FFMA2 path) ----
#define FMA2(d,a,b,c)   asm("fma.rn.f32x2 %0, %1, %2, %3;" : "=l"(d) : "l"(a), "l"(b), "l"(c))
#define ADD2(d,a,b)     asm("add.rn.f32x2 %0, %1, %2;"     : "=l"(d) : "l"(a), "l"(b))
#define PACK2(d,lo,hi)  asm("mov.b64 %0, {%1, %2};"        : "=l"(d) : "f"(lo), "f"(hi))
#define UNPACK2(lo,hi,s) asm("mov.b64 {%0, %1}, %2;"       : "=f"(lo), "=f"(hi) : "l"(s))

// x-projection dot: 64-wide, weights in regs, x broadcast from smem
__device__ __forceinline__ float proj_dot(const float* __restrict__ xrow,
                                          const unsigned long long* w, float bias)
{
    const ulonglong2* hp = (const ulonglong2*)xrow;
    unsigned long long a0, a1 = 0ull;
    PACK2(a0, bias, 0.f);
    #pragma unroll
    for (int k = 0; k < 16; k++) {
        ulonglong2 v = hp[k];
        FMA2(a0, w[2*k],     v.x, a0);
        FMA2(a1, w[2*k + 1], v.y, a1);
    }
    ADD2(a0, a0, a1);
    float lo, hi; UNPACK2(lo, hi, a0);
    return lo + hi;
}

__global__ __launch_bounds__(NTHR, 1) void fused_lstm_ws(
    const float* __restrict__ x,     const float* __restrict__ W_ih,
    const float* __restrict__ W_hh,  const float* __restrict__ b_ih,
    const float* __restrict__ b_hh,  const float* __restrict__ gamma,
    const float* __restrict__ beta,  const float* __restrict__ fc_w,
    const float* __restrict__ fc_b,  float* __restrict__ out)
{
    __shared__ __align__(16) float sh_h[BPB][H_ + 2];      // h (padded to 68)
    __shared__ __align__(16) float sh_x[2][BPB][D_];       // double-buffered x rows
    __shared__ __align__(16) float sh_xp[2][BPB][G4];      // double-buffered x-projection
    __shared__ __align__(16) float sh_g[BPB][G4];          // activated gates
    __shared__ float s_a[H_], s_b[H_];
    __shared__ unsigned s_last;

    const int tid = threadIdx.x;
    const int b0  = blockIdx.x * BPB;
    const bool is_gate = (tid < GATE_T);
    const int g   = tid;               // gate-role id (active < 264)
    const int pg  = tid - GATE_T;      // proj-role id (active < 264)

    // Unified weight registers: gate role -> W_hh row; proj role -> W_ih row.
    // Single array => single live range => 68 regs, not 132.
    unsigned long long w[34];
    float bias = 0.f;
    if (is_gate) {
        if (g < G4) {
            const float* wr = W_hh + (size_t)g * H_;
            #pragma unroll
            for (int i = 0; i < 33; i++) PACK2(w[i], wr[2*i], wr[2*i + 1]);
            PACK2(w[33], 0.f, 0.f);    // zero pad covers sh_h[66..67]
        }
    } else {
        if (pg < G4) {
            const ulonglong2* wp = (const ulonglong2*)(W_ih + (size_t)pg * D_);
            #pragma unroll
            for (int i = 0; i < 16; i++) { ulonglong2 v = wp[i]; w[2*i] = v.x; w[2*i+1] = v.y; }
            bias = b_ih[pg] + b_hh[pg];
        }
    }

    // init h (incl. pads), stage x(0) -> sh_x[0], x(1) -> sh_x[1]
    for (int i = tid; i < BPB * (H_ + 2); i += NTHR) ((float*)sh_h)[i] = 0.f;
    if (tid < 2 * BPB * (D_ / 4)) {                 // 128 threads, one float4 each
        const int buf = tid >> 6, idx = tid & 63, q = idx >> 4, e = idx & 15;
        ((float4*)sh_x[buf][q])[e] =
            ((const float4*)(x + ((size_t)(b0 + q) * T_ + buf) * D_))[e];
    }
    __syncthreads();

    // prologue: xp(0) -> sh_xp[0]
    if (!is_gate && pg < G4) {
        #pragma unroll
        for (int q = 0; q < BPB; q++)
            sh_xp[0][q][pg] = proj_dot(sh_x[0][q], w, bias);
    }
    __syncthreads();

    float c_ = 0.f, h_ = 0.f;
    const int q0 = (tid < G4) ? tid / H_ : 0;
    const int r  = (tid < G4) ? tid % H_ : 0;
    const bool tg = (g >= 2 * H_) && (g < 3 * H_);  // tanh gate?

    for (int t = 0; t < T_; t++) {
        const int pc = t & 1, pn = (t + 1) & 1;
        if (is_gate) {
            // ---- gate group: pre-activations + activations for 4 batches ----
            if (g < G4) {
                #pragma unroll
                for (int q = 0; q < BPB; q++) {
                    const ulonglong2* hp = (const ulonglong2*)sh_h[q];
                    unsigned long long a0 = 0ull, a1 = 0ull;
                    #pragma unroll
                    for (int k = 0; k < 17; k++) {
                        ulonglong2 v = hp[k];
                        FMA2(a0, w[2*k],     v.x, a0);
                        FMA2(a1, w[2*k + 1], v.y, a1);
                    }
                    ADD2(a0, a0, a1);
                    float lo, hi; UNPACK2(lo, hi, a0);
                    const float pre = lo + hi + sh_xp[pc][q][g];
                    const float arg = tg ? (-2.f * pre) : (-pre);
                    const float e   = __expf(arg);
                    const float s   = __fdividef(1.f, 1.f + e);
                    sh_g[q][g] = tg ? (2.f * s - 1.f) : s;
                }
            }
            asm volatile("bar.sync 1, 288;" ::: "memory");   // gate-group barrier
            if (tid < G4) {                                   // (q0, r) cell update
                const float i_ = sh_g[q0][r];
                const float f_ = sh_g[q0][H_ + r];
                const float gg = sh_g[q0][2 * H_ + r];
                const float o_ = sh_g[q0][3 * H_ + r];
                c_ = f_ * c_ + i_ * gg;
                const float e2 = __expf(-2.f * c_);
                const float th = __fdividef(2.f, 1.f + e2) - 1.f;
                h_ = o_ * th;
                sh_h[q0][r] = h_;
            }
        } else {
            // ---- proj group: prefetch x(t+2), compute xp(t+1) ----
            float4 pre4;
            const bool do_pre = (pg < BPB * (D_ / 4)) && (t + 2 < T_);
            const int q = pg >> 4, e = pg & 15;
            if (do_pre)
                pre4 = ((const float4*)(x + ((size_t)(b0 + q) * T_ + (t + 2)) * D_))[e];
            if (pg < G4 && t + 1 < T_) {
                #pragma unroll
                for (int qq = 0; qq < BPB; qq++)
                    sh_xp[pn][qq][pg] = proj_dot(sh_x[pn][qq], w, bias);
            }
            if (do_pre)
                ((float4*)sh_x[pc][q])[e] = pre4;   // x(t+2) into retired buffer
        }
        __syncthreads();   // publishes h(t), xp(t+1), x(t+2)
    }

    // ---- publish h_T; elect last block ----
    if (is_gate && tid < G4)
        g_hT[(b0 + q0) * H_ + r] = h_;
    __threadfence();
    __syncthreads();
    if (tid == 0) {
        unsigned old = atomicAdd(&g_done, 1);
        s_last = (old == NBLK - 1) ? 1u : 0u;
    }
    __syncthreads();
    if (!s_last) return;
    if (tid == 0) g_done = 0;            // reset for deterministic graph replay
    __threadfence();

    // ---- BN stats (last block) ----
    if (tid < G4) {
        float s = 0.f, qs = 0.f;
        for (int b = q0 * (B_ / BPB); b < (q0 + 1) * (B_ / BPB); b++) {
            const float v = g_hT[b * H_ + r];
            s += v; qs += v * v;
        }
        sh_g[q0][r] = s;
        sh_h[q0][r] = qs;
    }
    __syncthreads();
    if (tid < H_) {
        const float S = sh_g[0][tid] + sh_g[1][tid] + sh_g[2][tid] + sh_g[3][tid];
        const float Q = sh_h[0][tid] + sh_h[1][tid] + sh_h[2][tid] + sh_h[3][tid];
        const float mean = S * (1.f / B_);
        const float var  = Q * (1.f / B_) - mean * mean;
        const float a    = gamma[tid] * rsqrtf(var + 1e-5f);
        s_a[tid] = a * fc_w[tid];
        s_b[tid] = (beta[tid] - mean * a) * fc_w[tid];
    }
    __syncthreads();

    // ---- head ----
    const float f0 = fc_b[0];
    for (int b = tid; b < B_; b += NTHR) {
        float acc = f0;
        #pragma unroll
        for (int j = 0; j < H_; j++)
            acc += s_a[j] * g_hT[b * H_ + j] + s_b[j];
        out[b] = acc;
    }
}

extern "C" void kernel_launch(void* const* d_in, const int* in_sizes, int n_in,
                              void* d_out, int out_size)
{
    const float* x     = (const float*)d_in[0];
    const float* W_ih  = (const float*)d_in[1];
    const float* W_hh  = (const float*)d_in[2];
    const float* b_ih  = (const float*)d_in[3];
    const float* b_hh  = (const float*)d_in[4];
    const float* gamma = (const float*)d_in[5];
    const float* beta  = (const float*)d_in[6];
    const float* fc_w  = (const float*)d_in[7];
    const float* fc_b  = (const float*)d_in[8];
    float* out = (float*)d_out;

    fused_lstm_ws<<<NBLK, NTHR>>>(x, W_ih, W_hh, b_ih, b_hh,
                                  gamma, beta, fc_w, fc_b, out);
}